// round 11
// baseline (speedup 1.0000x reference)
#include <cuda_runtime.h>
#include <cuda_fp16.h>
#include <cstdint>

#define B_   8
#define N_   2048
#define DIN  256
#define HID  64
#define TI   128
#define CH   32
#define NCH  (N_ / CH)
#define KPG  (NCH / 2)        // chunks per warpgroup (32)
#define NSUP (KPG / 4)        // supers per group (8)
#define L2E  1.4426950408889634f

// dynamic SMEM layout
// adj: 16 warps x 3 slots x (16 rows x 144B) — warp-private rings
#define AW_SLOT 2304
#define AW_RING (3 * AW_SLOT)               // 6912
#define ABYTES  (16 * AW_RING)              // 110592
// B: 2 groups x 2 bufs x 4 tiles x (32 x 144)
#define B_TILE  4608
#define B_BUF   (4 * B_TILE)                // 18432
#define BOFF    ABYTES
#define BBYTES  (2 * 2 * B_BUF)             // 73728
#define F2EOFF  (BOFF + BBYTES)             // 184320
#define SMEM_DYN (F2EOFF + N_ * 4)          // 192512

// Scratch (device globals — no allocation allowed)
__device__ uint32_t g_Whh[B_ * N_ * HID / 2];       // fp16x2 Wh  [node][h/2]
__device__ float g_f1e[B_ * N_], g_f1s[B_ * N_];    // f1*log2e, 0.2*f1*log2e (f1s unused by main)
__device__ float g_f2e[B_ * N_], g_f2s[B_ * N_];

// ---------------- helpers ----------------
static __device__ __forceinline__ uint32_t smem_u32(const void* p) {
    uint32_t a;
    asm("{ .reg .u64 t; cvta.to.shared.u64 t, %1; cvt.u32.u64 %0, t; }"
        : "=r"(a) : "l"(p));
    return a;
}
static __device__ __forceinline__ float ex2(float x) {
    float y;
    asm("ex2.approx.f32 %0, %1;" : "=f"(y) : "f"(x));
    return y;
}
static __device__ __forceinline__ uint32_t pack2h(float w0, float w1) {
    uint32_t r;
    asm("cvt.rn.f16x2.f32 %0, %1, %2;" : "=r"(r) : "f"(w1), "f"(w0));
    return r;
}
static __device__ __forceinline__ void ldsm4t(uint32_t& r0, uint32_t& r1,
                                              uint32_t& r2, uint32_t& r3,
                                              uint32_t a) {
    asm volatile("ldmatrix.sync.aligned.m8n8.x4.trans.shared.b16 {%0,%1,%2,%3}, [%4];"
                 : "=r"(r0), "=r"(r1), "=r"(r2), "=r"(r3) : "r"(a));
}
static __device__ __forceinline__ void lds64(int2& v, uint32_t a) {
    asm volatile("ld.shared.v2.u32 {%0,%1}, [%2];" : "=r"(v.x), "=r"(v.y) : "r"(a));
}
static __device__ __forceinline__ void mma16816(float* c, const uint32_t* a,
                                                uint32_t b0, uint32_t b1) {
    asm volatile(
        "mma.sync.aligned.m16n8k16.row.col.f32.f16.f16.f32 "
        "{%0,%1,%2,%3}, {%4,%5,%6,%7}, {%8,%9}, {%0,%1,%2,%3};"
        : "+f"(c[0]), "+f"(c[1]), "+f"(c[2]), "+f"(c[3])
        : "r"(a[0]), "r"(a[1]), "r"(a[2]), "r"(a[3]), "r"(b0), "r"(b1));
}
#define CP_ASYNC16(dst, src) \
    asm volatile("cp.async.cg.shared.global [%0], [%1], 16;" :: "r"(dst), "l"(src) : "memory")
#define CP_COMMIT()  asm volatile("cp.async.commit_group;" ::: "memory")
#define CP_WAIT1()   asm volatile("cp.async.wait_group 1;" ::: "memory")
#define CP_WAIT0()   asm volatile("cp.async.wait_group 0;" ::: "memory")
#define GBAR(id)     asm volatile("bar.sync %0, 256;" :: "r"(id) : "memory")

// ---------------------------------------------------------------------------
// Kernel A: Wh = X @ W ; emits packed fp16x2 Wh AND per-node f1/f2 factors.
// ---------------------------------------------------------------------------
__global__ __launch_bounds__(256, 2) void gemm_wh(const float* __restrict__ X,
                                                  const float* __restrict__ W,
                                                  const float* __restrict__ a) {
    __shared__ __align__(16) float Xs[2][64][36];
    __shared__ __align__(16) float Ws[2][32][64];

    const int tid = threadIdx.x;
    const int tx = tid & 15;
    const int ty = tid >> 4;
    const int r0 = blockIdx.x * 64;
    const int xr = tid >> 3, xk = (tid & 7) << 2;
    const int wk = tid >> 4, wh_ = (tid & 15) << 2;

    float acc[4][4];
#pragma unroll
    for (int i = 0; i < 4; i++)
#pragma unroll
        for (int j = 0; j < 4; j++) acc[i][j] = 0.f;

    float4 xv0, xv1, wv0, wv1;
    xv0 = *(const float4*)(X + (size_t)(r0 + xr) * DIN + xk);
    xv1 = *(const float4*)(X + (size_t)(r0 + 32 + xr) * DIN + xk);
    wv0 = *(const float4*)(W + (size_t)wk * HID + wh_);
    wv1 = *(const float4*)(W + (size_t)(16 + wk) * HID + wh_);
    *(float4*)&Xs[0][xr][xk]      = xv0;
    *(float4*)&Xs[0][32 + xr][xk] = xv1;
    *(float4*)&Ws[0][wk][wh_]      = wv0;
    *(float4*)&Ws[0][16 + wk][wh_] = wv1;
    __syncthreads();

    for (int kt = 0; kt < 8; kt++) {
        const int cur = kt & 1, nxt = cur ^ 1;
        if (kt < 7) {
            const int k0 = (kt + 1) * 32;
            xv0 = *(const float4*)(X + (size_t)(r0 + xr) * DIN + k0 + xk);
            xv1 = *(const float4*)(X + (size_t)(r0 + 32 + xr) * DIN + k0 + xk);
            wv0 = *(const float4*)(W + (size_t)(k0 + wk) * HID + wh_);
            wv1 = *(const float4*)(W + (size_t)(k0 + 16 + wk) * HID + wh_);
        }
#pragma unroll
        for (int k = 0; k < 32; k++) {
            float4 wv = *(float4*)&Ws[cur][k][tx << 2];
#pragma unroll
            for (int rr = 0; rr < 4; rr++) {
                float xv = Xs[cur][(ty << 2) + rr][k];
                acc[rr][0] += xv * wv.x;
                acc[rr][1] += xv * wv.y;
                acc[rr][2] += xv * wv.z;
                acc[rr][3] += xv * wv.w;
            }
        }
        if (kt < 7) {
            *(float4*)&Xs[nxt][xr][xk]      = xv0;
            *(float4*)&Xs[nxt][32 + xr][xk] = xv1;
            *(float4*)&Ws[nxt][wk][wh_]      = wv0;
            *(float4*)&Ws[nxt][16 + wk][wh_] = wv1;
        }
        __syncthreads();
    }

    // fp16 Wh output
#pragma unroll
    for (int rr = 0; rr < 4; rr++) {
        const int node = r0 + (ty << 2) + rr;
        size_t o = (size_t)node * 32 + tx * 2;
        *(uint2*)&g_Whh[o] = make_uint2(pack2h(acc[rr][0], acc[rr][1]),
                                        pack2h(acc[rr][2], acc[rr][3]));
    }

    // fused f1/f2 epilogue
    const float4 a1 = *(const float4*)(a + (tx << 2));
    const float4 a2 = *(const float4*)(a + HID + (tx << 2));
    float p1[4], p2[4];
#pragma unroll
    for (int rr = 0; rr < 4; rr++) {
        p1[rr] = acc[rr][0] * a1.x + acc[rr][1] * a1.y +
                 acc[rr][2] * a1.z + acc[rr][3] * a1.w;
        p2[rr] = acc[rr][0] * a2.x + acc[rr][1] * a2.y +
                 acc[rr][2] * a2.z + acc[rr][3] * a2.w;
#pragma unroll
        for (int s = 8; s > 0; s >>= 1) {
            p1[rr] += __shfl_xor_sync(0xffffffffu, p1[rr], s);
            p2[rr] += __shfl_xor_sync(0xffffffffu, p2[rr], s);
        }
    }
    if (tx == 0) {
#pragma unroll
        for (int rr = 0; rr < 4; rr++) {
            const int node = r0 + (ty << 2) + rr;
            g_f1e[node] = p1[rr] * L2E;
            g_f1s[node] = 0.2f * p1[rr] * L2E;
            g_f2e[node] = p2[rr] * L2E;
            g_f2s[node] = 0.2f * p2[rr] * L2E;
        }
    }
}

// ---------------------------------------------------------------------------
// Main kernel: masked-softmax attention * Wh via mma.sync fp16.
// 512 threads, 2 groups (even/odd chunks). FREE-RUNNING WARPS:
//   - adj: warp-private 3-slot cp.async ring (4 segs/thread/chunk — same copy
//     cost as shared tiles); readiness = own wait_group(1) + __syncwarp.
//     No inter-warp barrier in the chunk loop.
//   - B (Wh fp16): 4-chunk super-tiles, double buffered per group; one named
//     barrier per 4 chunks (cp.async wait + bar pattern).
//   - leakyrelu exponent: m = fmax(fe, 0.2*fe); f2s table eliminated.
// ---------------------------------------------------------------------------
__global__ __launch_bounds__(512) void gat_main(const int* __restrict__ adj,
                                                float* __restrict__ out) {
    extern __shared__ __align__(16) char sm[];
    const uint32_t smb = smem_u32(sm);
    float* f2e_s = (float*)(sm + F2EOFF);

    const int tid = threadIdx.x;
    const int wg = tid >> 8;                 // warpgroup 0/1 (even/odd chunks)
    const int wtid = tid & 255;
    const int lane = tid & 31;
    const int w = tid >> 5;                  // global warp 0..15
    const int w8 = w & 7;                    // warp-in-group
    const int g = lane >> 2, tg = lane & 3;
    const int b = blockIdx.x >> 4;
    const int i0 = (blockIdx.x & 15) * TI;
    const int base = b * N_;

    const int r_lo = w8 * 16 + g, r_hi = r_lo + 8;

    const int* adjb = adj + (size_t)b * N_ * N_ + (size_t)i0 * N_;
    const uint32_t* whh = g_Whh + (size_t)base * 32;

    // warp-private adj ring
    const uint32_t aring = smb + w * AW_RING;
    // group B region
    const uint32_t bgrp = smb + BOFF + wg * (2 * B_BUF);

    // adj copy mapping: thread copies row (lane>>1) of its warp's 16-row band
    const int crow = w8 * 16 + (lane >> 1);                 // row within i-tile
    const uint32_t adst = aring + (lane >> 1) * 144 + (lane & 1) * 64;  // +slot*AW_SLOT +q*16
    const int* asrc = adjb + (size_t)crow * N_ + (lane & 1) * 16;       // +ch*CH +q*4

    // B copy mapping: thread owns tile (wtid>>6), row (wtid&63)>>1
    const int btile_i = wtid >> 6;
    const int bl = wtid & 63;
    const uint32_t bdst = bgrp + btile_i * B_TILE + (bl >> 1) * 144 + (bl & 1) * 64;  // +buf*B_BUF +q*16
    const uint32_t* bsrc = whh + (size_t)(bl >> 1) * 32 + (bl & 1) * 16;              // +j0*32 +q*4

    // stage f2e table (512 threads x 1 float4)
    {
        const int idx = tid * 4;
        *(float4*)&f2e_s[idx] = *(const float4*)(g_f2e + base + idx);
    }

    // ---- prologue ----
    // group P0: adj(0) + B super 0 ; group P1: adj(1)
    {
        const int ch0 = wg;                   // group chunk 0 -> global chunk
#pragma unroll
        for (int q = 0; q < 4; q++)
            CP_ASYNC16(adst + 0 * AW_SLOT + q * 16, asrc + (size_t)ch0 * CH + q * 4);
        {
            const int ch = 2 * btile_i + wg;  // super 0 tiles
            const uint32_t* s = bsrc + (size_t)(ch * CH) * 32;
#pragma unroll
            for (int q = 0; q < 4; q++)
                CP_ASYNC16(bdst + 0 * B_BUF + q * 16, s + q * 4);
        }
        CP_COMMIT();
        const int ch1 = 2 + wg;
#pragma unroll
        for (int q = 0; q < 4; q++)
            CP_ASYNC16(adst + 1 * AW_SLOT + q * 16, asrc + (size_t)ch1 * CH + q * 4);
        CP_COMMIT();
    }
    __syncthreads();   // f2e table visible to all

    const float f1e_lo = g_f1e[base + i0 + r_lo];
    const float f1e_hi = g_f1e[base + i0 + r_hi];
    float dlo = 0.f, dhi = 0.f;

    float c[8][4];
#pragma unroll
    for (int nt = 0; nt < 8; nt++)
#pragma unroll
        for (int q = 0; q < 4; q++) c[nt][q] = 0.f;

    const uint32_t bar_id = wg + 1;

    for (int k = 0; k < KPG; k++) {
        CP_WAIT1();          // own adj(k) (and B(super) at boundary) complete
        __syncwarp();
        if ((k & 3) == 0) GBAR(bar_id);   // publish B super (k>>2) group-wide

        // issue adj(k+2) into private ring
        if (k + 2 < KPG) {
            const int ch = 2 * (k + 2) + wg;
            const uint32_t d = adst + ((k + 2) % 3) * AW_SLOT;
            const int* srcp = asrc + (size_t)ch * CH;
#pragma unroll
            for (int q = 0; q < 4; q++)
                CP_ASYNC16(d + q * 16, srcp + q * 4);
        }
        // at super boundary issue B(s+1)
        if ((k & 3) == 0 && (k >> 2) + 1 < NSUP) {
            const int s1 = (k >> 2) + 1;
            const int ch = 2 * (4 * s1 + btile_i) + wg;
            const uint32_t d = bdst + (s1 & 1) * B_BUF;
            const uint32_t* s = bsrc + (size_t)(ch * CH) * 32;
#pragma unroll
            for (int q = 0; q < 4; q++)
                CP_ASYNC16(d + q * 16, s + q * 4);
        }
        CP_COMMIT();

        const uint32_t aslot = aring + (k % 3) * AW_SLOT;
        const int jb0 = (2 * k + wg) * CH;

        // stage1: attention-weight A-fragments (fp32 math, one fp16 rounding)
        uint32_t ah[2][4];
#pragma unroll
        for (int s = 0; s < 2; s++) {
            const int co = s * 64 + tg * 8;
            int2 alo0, alo8, ahi0, ahi8;
            lds64(alo0, aslot + g * 144 + co);
            lds64(alo8, aslot + g * 144 + co + 32);
            lds64(ahi0, aslot + (g + 8) * 144 + co);
            lds64(ahi8, aslot + (g + 8) * 144 + co + 32);

            const int jb = jb0 + s * 16 + 2 * tg;
            const float2 e01 = *(const float2*)&f2e_s[jb];
            const float2 e89 = *(const float2*)&f2e_s[jb + 8];

            float fe;
            fe = f1e_lo + e01.x;
            float wl0 = (alo0.x > 0) ? ex2(fmaxf(fe, 0.2f * fe)) : 0.f;
            fe = f1e_lo + e01.y;
            float wl1 = (alo0.y > 0) ? ex2(fmaxf(fe, 0.2f * fe)) : 0.f;
            fe = f1e_lo + e89.x;
            float wl8 = (alo8.x > 0) ? ex2(fmaxf(fe, 0.2f * fe)) : 0.f;
            fe = f1e_lo + e89.y;
            float wl9 = (alo8.y > 0) ? ex2(fmaxf(fe, 0.2f * fe)) : 0.f;
            fe = f1e_hi + e01.x;
            float wh0 = (ahi0.x > 0) ? ex2(fmaxf(fe, 0.2f * fe)) : 0.f;
            fe = f1e_hi + e01.y;
            float wh1 = (ahi0.y > 0) ? ex2(fmaxf(fe, 0.2f * fe)) : 0.f;
            fe = f1e_hi + e89.x;
            float wh8 = (ahi8.x > 0) ? ex2(fmaxf(fe, 0.2f * fe)) : 0.f;
            fe = f1e_hi + e89.y;
            float wh9 = (ahi8.y > 0) ? ex2(fmaxf(fe, 0.2f * fe)) : 0.f;

            dlo += (wl0 + wl1) + (wl8 + wl9);
            dhi += (wh0 + wh1) + (wh8 + wh9);

            ah[s][0] = pack2h(wl0, wl1);
            ah[s][1] = pack2h(wh0, wh1);
            ah[s][2] = pack2h(wl8, wl9);
            ah[s][3] = pack2h(wh8, wh9);
        }

        // ldmatrix B fragments + 16 mma per chunk
        const uint32_t btile = bgrp + ((k >> 2) & 1) * B_BUF + (k & 3) * B_TILE;
        const uint32_t b_rd = btile + (lane & 15) * 144 + ((lane >> 4) << 4);
#pragma unroll
        for (int s = 0; s < 2; s++) {
#pragma unroll
            for (int n16 = 0; n16 < 4; n16++) {
                uint32_t b0, b1, b2, b3;
                ldsm4t(b0, b1, b2, b3, b_rd + s * 16 * 144 + n16 * 32);
                mma16816(c[n16 * 2],     ah[s], b0, b1);
                mma16816(c[n16 * 2 + 1], ah[s], b2, b3);
            }
        }
    }

    // ---- merge the two groups' partials ----
    dlo += __shfl_xor_sync(0xffffffffu, dlo, 1);
    dlo += __shfl_xor_sync(0xffffffffu, dlo, 2);
    dhi += __shfl_xor_sync(0xffffffffu, dhi, 1);
    dhi += __shfl_xor_sync(0xffffffffu, dhi, 2);

    CP_WAIT0();
    __syncthreads();   // both pipelines done; SMEM reusable

    float* cbuf = (float*)sm;                   // 128 x 64 fp32 = 32KB
    float* dbuf = (float*)(sm + 32768);         // 128 floats

    if (wg == 1) {
#pragma unroll
        for (int nt = 0; nt < 8; nt++) {
            const int col = nt * 8 + 2 * tg;
            cbuf[r_lo * 64 + col]     = c[nt][0];
            cbuf[r_lo * 64 + col + 1] = c[nt][1];
            cbuf[r_hi * 64 + col]     = c[nt][2];
            cbuf[r_hi * 64 + col + 1] = c[nt][3];
        }
        if (tg == 0) {
            dbuf[r_lo] = dlo;
            dbuf[r_hi] = dhi;
        }
    }
    __syncthreads();

    if (wg == 0) {
        const float rlo = __fdividef(1.f, dlo + dbuf[r_lo]);
        const float rhi = __fdividef(1.f, dhi + dbuf[r_hi]);
        float* olo = out + (size_t)(base + i0 + r_lo) * HID;
        float* ohi = out + (size_t)(base + i0 + r_hi) * HID;
#pragma unroll
        for (int nt = 0; nt < 8; nt++) {
            const int col = nt * 8 + 2 * tg;
            *(float2*)&olo[col] = make_float2((c[nt][0] + cbuf[r_lo * 64 + col]) * rlo,
                                              (c[nt][1] + cbuf[r_lo * 64 + col + 1]) * rlo);
            *(float2*)&ohi[col] = make_float2((c[nt][2] + cbuf[r_hi * 64 + col]) * rhi,
                                              (c[nt][3] + cbuf[r_hi * 64 + col + 1]) * rhi);
        }
    }
}

// ---------------------------------------------------------------------------
extern "C" void kernel_launch(void* const* d_in, const int* in_sizes, int n_in,
                              void* d_out, int out_size) {
    const float* X  = (const float*)d_in[0];   // node_features [8,2048,256]
    const int*   A  = (const int*)d_in[1];     // adj [8,2048,2048]
    const float* W  = (const float*)d_in[2];   // W [256,64]
    const float* av = (const float*)d_in[3];   // a [128,1]
    float* out = (float*)d_out;                // [8,2048,64] f32

    cudaFuncSetAttribute(gat_main, cudaFuncAttributeMaxDynamicSharedMemorySize,
                         SMEM_DYN);

    gemm_wh<<<(B_ * N_) / 64, 256>>>(X, W, av);
    gat_main<<<dim3(B_ * (N_ / TI)), 512, SMEM_DYN>>>(A, out);
}

// round 12
// speedup vs baseline: 1.3269x; 1.3269x over previous
#include <cuda_runtime.h>
#include <cuda_fp16.h>
#include <cstdint>

#define B_   8
#define N_   2048
#define DIN  256
#define HID  64
#define TI   128
#define CH   32
#define NCH  (N_ / CH)
#define KPG  (NCH / 2)        // chunks per warpgroup (32)
#define L2E  1.4426950408889634f

// ---- gat_main dynamic SMEM (R10 layout, f2s table removed) ----
#define SLOT_A  (128 * 144)                 // adj tile: 128 rows x 32 ints, 144B-padded
#define ABYTES  (8 * SLOT_A)                // 2 groups x 4 slots = 147456
#define SLOT_B  (32 * 144)                  // B tile: 32 nodes x 64 fp16, 144B-padded
#define BOFF    ABYTES
#define BBYTES  (8 * SLOT_B)                // 36864
#define F2EOFF  (BOFF + BBYTES)             // 184320
#define SMEM_DYN (F2EOFF + N_ * 4)          // 192512

// ---- gemm_wh dynamic SMEM ----
#define GW_WOFF  0                          // W fp16 [256][72]  = 36864
#define GW_XOFF  36864                      // X ring: 4 slots x (128 x 144B)
#define GW_XSLOT 18432
#define SMEM_GW  (GW_XOFF + 4 * GW_XSLOT)   // 110592

// Scratch (device globals — no allocation allowed)
__device__ uint32_t g_Whh[B_ * N_ * HID / 2];       // fp16x2 Wh  [node][h/2]
__device__ float g_f1e[B_ * N_];                    // f1*log2e
__device__ float g_f2e[B_ * N_];                    // f2*log2e

// ---------------- helpers ----------------
static __device__ __forceinline__ uint32_t smem_u32(const void* p) {
    uint32_t a;
    asm("{ .reg .u64 t; cvta.to.shared.u64 t, %1; cvt.u32.u64 %0, t; }"
        : "=r"(a) : "l"(p));
    return a;
}
static __device__ __forceinline__ float ex2(float x) {
    float y;
    asm("ex2.approx.f32 %0, %1;" : "=f"(y) : "f"(x));
    return y;
}
static __device__ __forceinline__ uint32_t pack2h(float w0, float w1) {
    uint32_t r;
    asm("cvt.rn.f16x2.f32 %0, %1, %2;" : "=r"(r) : "f"(w1), "f"(w0));
    return r;
}
// split pair into fp16 hi + fp16 lo (exact residual, ~2^-22 rel)
static __device__ __forceinline__ void split2h(float w0, float w1,
                                               uint32_t& hi, uint32_t& lo) {
    uint32_t h = pack2h(w0, w1);
    float h0, h1;
    asm("{ .reg .f16 a,b; mov.b32 {a,b}, %2; cvt.f32.f16 %0, a; cvt.f32.f16 %1, b; }"
        : "=f"(h0), "=f"(h1) : "r"(h));
    lo = pack2h(w0 - h0, w1 - h1);
    hi = h;
}
static __device__ __forceinline__ void ldsm4t(uint32_t& r0, uint32_t& r1,
                                              uint32_t& r2, uint32_t& r3,
                                              uint32_t a) {
    asm volatile("ldmatrix.sync.aligned.m8n8.x4.trans.shared.b16 {%0,%1,%2,%3}, [%4];"
                 : "=r"(r0), "=r"(r1), "=r"(r2), "=r"(r3) : "r"(a));
}
static __device__ __forceinline__ void lds64(int2& v, uint32_t a) {
    asm volatile("ld.shared.v2.u32 {%0,%1}, [%2];" : "=r"(v.x), "=r"(v.y) : "r"(a));
}
static __device__ __forceinline__ void lds64f(float2& v, uint32_t a) {
    asm volatile("ld.shared.v2.f32 {%0,%1}, [%2];" : "=f"(v.x), "=f"(v.y) : "r"(a));
}
static __device__ __forceinline__ void mma16816(float* c, const uint32_t* a,
                                                uint32_t b0, uint32_t b1) {
    asm volatile(
        "mma.sync.aligned.m16n8k16.row.col.f32.f16.f16.f32 "
        "{%0,%1,%2,%3}, {%4,%5,%6,%7}, {%8,%9}, {%0,%1,%2,%3};"
        : "+f"(c[0]), "+f"(c[1]), "+f"(c[2]), "+f"(c[3])
        : "r"(a[0]), "r"(a[1]), "r"(a[2]), "r"(a[3]), "r"(b0), "r"(b1));
}
#define CP_ASYNC16(dst, src) \
    asm volatile("cp.async.cg.shared.global [%0], [%1], 16;" :: "r"(dst), "l"(src) : "memory")
#define CP_COMMIT()  asm volatile("cp.async.commit_group;" ::: "memory")
#define CP_WAIT2()   asm volatile("cp.async.wait_group 2;" ::: "memory")
#define CP_WAIT0()   asm volatile("cp.async.wait_group 0;" ::: "memory")
#define GBAR(id)     asm volatile("bar.sync %0, 256;" :: "r"(id) : "memory")

// ---------------------------------------------------------------------------
// Kernel A: Wh = X @ W via mma.sync fp16, 2-term split (Xhi·W + Xlo·W, exact
// X split; only W's fp16 rounding remains ~2^-11 rel). Emits packed fp16x2 Wh
// and per-node f1/f2 exponent factors. Grid 128 x 256 threads, 8 warps;
// warp w: rows w*16..w*16+15. X staged via 4-slot cp.async ring (fp32),
// A-fragments built by LDS.64 + split; W converted once to fp16 SMEM.
// ---------------------------------------------------------------------------
__global__ __launch_bounds__(256) void gemm_wh(const float* __restrict__ X,
                                               const float* __restrict__ W,
                                               const float* __restrict__ a) {
    extern __shared__ __align__(16) char smw[];
    const uint32_t smb = smem_u32(smw);
    const uint32_t wsb = smb + GW_WOFF;
    const uint32_t xsb = smb + GW_XOFF;

    const int tid = threadIdx.x;
    const int lane = tid & 31, w8 = tid >> 5;
    const int g = lane >> 2, tg = lane & 3;
    const int r0 = blockIdx.x * 128;

    // convert W (fp32 global) -> fp16 SMEM [256][72-halves rows = 144B]
#pragma unroll
    for (int i = 0; i < 16; i++) {
        const int e = (i * 256 + tid) * 4;      // flat float index
        const int k = e >> 6, n = e & 63;
        const float4 wv = *(const float4*)(W + e);
        *(uint32_t*)(smw + GW_WOFF + k * 144 + n * 2)     = pack2h(wv.x, wv.y);
        *(uint32_t*)(smw + GW_WOFF + k * 144 + n * 2 + 4) = pack2h(wv.z, wv.w);
    }

    // X ring copy mapping: thread -> row tid>>1, 64B half (tid&1), 4x16B segs
    const int xrow = tid >> 1;
    const uint32_t xdst = xsb + xrow * 144 + (tid & 1) * 64;        // +slot*GW_XSLOT +q*16
    const float* xsrc = X + (size_t)(r0 + xrow) * DIN + (tid & 1) * 16;  // +kc*32 +q*4

    // prologue: issue k-chunks 0..2
#pragma unroll
    for (int p = 0; p < 3; p++) {
#pragma unroll
        for (int q = 0; q < 4; q++)
            CP_ASYNC16(xdst + p * GW_XSLOT + q * 16, xsrc + p * 32 + q * 4);
        CP_COMMIT();
    }

    float c[8][4];
#pragma unroll
    for (int nt = 0; nt < 8; nt++)
#pragma unroll
        for (int q = 0; q < 4; q++) c[nt][q] = 0.f;

    for (int kc = 0; kc < 8; kc++) {
        CP_WAIT2();
        __syncthreads();     // chunk kc visible; closes WAR on slot (kc+3)&3
                             // (first iter also publishes W conversion)
        if (kc + 3 < 8) {
#pragma unroll
            for (int q = 0; q < 4; q++)
                CP_ASYNC16(xdst + ((kc + 3) & 3) * GW_XSLOT + q * 16,
                           xsrc + (kc + 3) * 32 + q * 4);
        }
        CP_COMMIT();

        const uint32_t xslot = xsb + (kc & 3) * GW_XSLOT;
#pragma unroll
        for (int s = 0; s < 2; s++) {
            // A fragments: rows w8*16+g (+8), k-cols s*16 + 2tg (+1, +8)
            const uint32_t abase = xslot + (w8 * 16 + g) * 144 + (s * 16 + 2 * tg) * 4;
            float2 x0, x1, x2, x3;
            lds64f(x0, abase);                  // a0: row g,   col 2tg
            lds64f(x1, abase + 8 * 144);        // a1: row g+8, col 2tg
            lds64f(x2, abase + 32);             // a2: row g,   col 2tg+8
            lds64f(x3, abase + 8 * 144 + 32);   // a3: row g+8, col 2tg+8
            uint32_t ahi[4], alo[4];
            split2h(x0.x, x0.y, ahi[0], alo[0]);
            split2h(x1.x, x1.y, ahi[1], alo[1]);
            split2h(x2.x, x2.y, ahi[2], alo[2]);
            split2h(x3.x, x3.y, ahi[3], alo[3]);

            const uint32_t brd = wsb + (kc * 32 + s * 16 + (lane & 15)) * 144 +
                                 ((lane >> 4) << 4);
#pragma unroll
            for (int n16 = 0; n16 < 4; n16++) {
                uint32_t b0, b1, b2, b3;
                ldsm4t(b0, b1, b2, b3, brd + n16 * 32);
                mma16816(c[n16 * 2],     ahi, b0, b1);
                mma16816(c[n16 * 2],     alo, b0, b1);
                mma16816(c[n16 * 2 + 1], ahi, b2, b3);
                mma16816(c[n16 * 2 + 1], alo, b2, b3);
            }
        }
    }

    // epilogue: fp16 Wh out + f1/f2 (quad-reduced dot with a1/a2)
    const int r_lo = w8 * 16 + g, r_hi = r_lo + 8;
    float p1lo = 0.f, p2lo = 0.f, p1hi = 0.f, p2hi = 0.f;
#pragma unroll
    for (int nt = 0; nt < 8; nt++) {
        const int col = nt * 8 + 2 * tg;
        const float a1x = a[col], a1y = a[col + 1];
        const float a2x = a[HID + col], a2y = a[HID + col + 1];
        p1lo += c[nt][0] * a1x + c[nt][1] * a1y;
        p2lo += c[nt][0] * a2x + c[nt][1] * a2y;
        p1hi += c[nt][2] * a1x + c[nt][3] * a1y;
        p2hi += c[nt][2] * a2x + c[nt][3] * a2y;
        g_Whh[(size_t)(r0 + r_lo) * 32 + nt * 4 + tg] = pack2h(c[nt][0], c[nt][1]);
        g_Whh[(size_t)(r0 + r_hi) * 32 + nt * 4 + tg] = pack2h(c[nt][2], c[nt][3]);
    }
#pragma unroll
    for (int s = 1; s <= 2; s <<= 1) {
        p1lo += __shfl_xor_sync(0xffffffffu, p1lo, s);
        p2lo += __shfl_xor_sync(0xffffffffu, p2lo, s);
        p1hi += __shfl_xor_sync(0xffffffffu, p1hi, s);
        p2hi += __shfl_xor_sync(0xffffffffu, p2hi, s);
    }
    if (tg == 0) {
        g_f1e[r0 + r_lo] = p1lo * L2E;
        g_f2e[r0 + r_lo] = p2lo * L2E;
        g_f1e[r0 + r_hi] = p1hi * L2E;
        g_f2e[r0 + r_hi] = p2hi * L2E;
    }
}

// ---------------------------------------------------------------------------
// Main kernel (R10-exact structure, 68.3us-verified): masked-softmax
// attention * Wh via mma.sync fp16. 512 threads = two 8-warp groups (even/odd
// chunks), group-private 4-slot cp.async rings, GBAR per chunk.
// Only change vs R10: leakyrelu exponent = fmax(fe, 0.2*fe); f2s table gone.
// ---------------------------------------------------------------------------
__global__ __launch_bounds__(512) void gat_main(const int* __restrict__ adj,
                                                float* __restrict__ out) {
    extern __shared__ __align__(16) char sm[];
    const uint32_t smb = smem_u32(sm);
    float* f2e_s = (float*)(sm + F2EOFF);

    const int tid = threadIdx.x;
    const int wg = tid >> 8;                 // warpgroup 0/1
    const int wtid = tid & 255;
    const int lane = tid & 31, w8 = wtid >> 5;   // warp-in-group 0..7
    const int g = lane >> 2, tg = lane & 3;
    const int b = blockIdx.x >> 4;
    const int i0 = (blockIdx.x & 15) * TI;
    const int base = b * N_;

    const int r_lo = w8 * 16 + g, r_hi = r_lo + 8;

    const int* adjb = adj + (size_t)b * N_ * N_ + (size_t)i0 * N_;
    const uint32_t* whh = g_Whh + (size_t)base * 32;

    // group-private ring bases
    const uint32_t agb = smb + wg * 4 * SLOT_A;
    const uint32_t bgb = smb + BOFF + wg * 4 * SLOT_B;

    // cp.async segment mapping (within group)
    const int arow = wtid >> 3, acol = (wtid & 7) * 4;
    const uint32_t a_woff = arow * 144 + acol * 4;           // +q*32*144
    const uint32_t b_woff = (wtid >> 3) * 144 + (wtid & 7) * 16;

    // stage f2e table (512 threads: one float4 each)
    {
        const int idx = tid * 4;
        *(float4*)&f2e_s[idx] = *(const float4*)(g_f2e + base + idx);
    }

    // prologue: each group issues its chunks k=0,1,2 (global ch = 2k+wg)
#pragma unroll
    for (int p = 0; p < 3; p++) {
        const int ch = 2 * p + wg;
        const uint32_t aslot = agb + p * SLOT_A;
        const uint32_t bslot = bgb + p * SLOT_B;
#pragma unroll
        for (int q = 0; q < 4; q++) {
            const int row = arow + q * 32;
            CP_ASYNC16(aslot + a_woff + q * 32 * 144,
                       adjb + (size_t)row * N_ + ch * CH + acol);
        }
        CP_ASYNC16(bslot + b_woff, whh + (size_t)(ch * CH + (wtid >> 3)) * 32 + (wtid & 7) * 4);
        CP_COMMIT();
    }
    __syncthreads();   // f2 table visible to both groups

    const float f1e_lo = g_f1e[base + i0 + r_lo];
    const float f1e_hi = g_f1e[base + i0 + r_hi];
    float dlo = 0.f, dhi = 0.f;

    float c[8][4];
#pragma unroll
    for (int nt = 0; nt < 8; nt++)
#pragma unroll
        for (int q = 0; q < 4; q++) c[nt][q] = 0.f;

    const uint32_t bar_id = wg + 1;

    for (int k = 0; k < KPG; k++) {
        CP_WAIT2();          // this group's chunk k complete
        GBAR(bar_id);        // group-local visibility; closes WAR on slot (k+3)&3

        // issue chunk k+3 (global ch = 2(k+3)+wg)
        if (k + 3 < KPG) {
            const int ch = 2 * (k + 3) + wg;
            const uint32_t aslot = agb + ((k + 3) & 3) * SLOT_A;
            const uint32_t bslot = bgb + ((k + 3) & 3) * SLOT_B;
#pragma unroll
            for (int q = 0; q < 4; q++) {
                const int row = arow + q * 32;
                CP_ASYNC16(aslot + a_woff + q * 32 * 144,
                           adjb + (size_t)row * N_ + ch * CH + acol);
            }
            CP_ASYNC16(bslot + b_woff,
                       whh + (size_t)(ch * CH + (wtid >> 3)) * 32 + (wtid & 7) * 4);
        }
        CP_COMMIT();         // keep group counter aligned

        const uint32_t adjslot = agb + (k & 3) * SLOT_A;
        const uint32_t bslot   = bgb + (k & 3) * SLOT_B;
        const int jb0 = (2 * k + wg) * CH;

        // stage1: attention-weight A-fragments (fp32 math, one fp16 rounding)
        uint32_t ah[2][4];
#pragma unroll
        for (int s = 0; s < 2; s++) {
            const int co = s * 64 + tg * 8;
            int2 alo0, alo8, ahi0, ahi8;
            lds64(alo0, adjslot + r_lo * 144 + co);
            lds64(alo8, adjslot + r_lo * 144 + co + 32);
            lds64(ahi0, adjslot + r_hi * 144 + co);
            lds64(ahi8, adjslot + r_hi * 144 + co + 32);

            const int jb = jb0 + s * 16 + 2 * tg;
            const float2 e01 = *(const float2*)&f2e_s[jb];
            const float2 e89 = *(const float2*)&f2e_s[jb + 8];

            float fe;
            fe = f1e_lo + e01.x;
            float wl0 = (alo0.x > 0) ? ex2(fmaxf(fe, 0.2f * fe)) : 0.f;
            fe = f1e_lo + e01.y;
            float wl1 = (alo0.y > 0) ? ex2(fmaxf(fe, 0.2f * fe)) : 0.f;
            fe = f1e_lo + e89.x;
            float wl8 = (alo8.x > 0) ? ex2(fmaxf(fe, 0.2f * fe)) : 0.f;
            fe = f1e_lo + e89.y;
            float wl9 = (alo8.y > 0) ? ex2(fmaxf(fe, 0.2f * fe)) : 0.f;
            fe = f1e_hi + e01.x;
            float wh0 = (ahi0.x > 0) ? ex2(fmaxf(fe, 0.2f * fe)) : 0.f;
            fe = f1e_hi + e01.y;
            float wh1 = (ahi0.y > 0) ? ex2(fmaxf(fe, 0.2f * fe)) : 0.f;
            fe = f1e_hi + e89.x;
            float wh8 = (ahi8.x > 0) ? ex2(fmaxf(fe, 0.2f * fe)) : 0.f;
            fe = f1e_hi + e89.y;
            float wh9 = (ahi8.y > 0) ? ex2(fmaxf(fe, 0.2f * fe)) : 0.f;

            dlo += (wl0 + wl1) + (wl8 + wl9);
            dhi += (wh0 + wh1) + (wh8 + wh9);

            ah[s][0] = pack2h(wl0, wl1);
            ah[s][1] = pack2h(wh0, wh1);
            ah[s][2] = pack2h(wl8, wl9);
            ah[s][3] = pack2h(wh8, wh9);
        }

        // ldmatrix B fragments + 16 mma per chunk
        const uint32_t b_rd = bslot + (lane & 15) * 144 + ((lane >> 4) << 4);
#pragma unroll
        for (int s = 0; s < 2; s++) {
#pragma unroll
            for (int n16 = 0; n16 < 4; n16++) {
                uint32_t b0, b1, b2, b3;
                ldsm4t(b0, b1, b2, b3, b_rd + s * 16 * 144 + n16 * 32);
                mma16816(c[n16 * 2],     ah[s], b0, b1);
                mma16816(c[n16 * 2 + 1], ah[s], b2, b3);
            }
        }
    }

    // ---- merge the two groups' partials ----
    dlo += __shfl_xor_sync(0xffffffffu, dlo, 1);
    dlo += __shfl_xor_sync(0xffffffffu, dlo, 2);
    dhi += __shfl_xor_sync(0xffffffffu, dhi, 1);
    dhi += __shfl_xor_sync(0xffffffffu, dhi, 2);

    CP_WAIT0();
    __syncthreads();   // both pipelines done; SMEM reusable

    float* cbuf = (float*)sm;                   // 128 x 64 fp32 = 32KB
    float* dbuf = (float*)(sm + 32768);         // 128 floats

    if (wg == 1) {
#pragma unroll
        for (int nt = 0; nt < 8; nt++) {
            const int col = nt * 8 + 2 * tg;
            cbuf[r_lo * 64 + col]     = c[nt][0];
            cbuf[r_lo * 64 + col + 1] = c[nt][1];
            cbuf[r_hi * 64 + col]     = c[nt][2];
            cbuf[r_hi * 64 + col + 1] = c[nt][3];
        }
        if (tg == 0) {
            dbuf[r_lo] = dlo;
            dbuf[r_hi] = dhi;
        }
    }
    __syncthreads();

    if (wg == 0) {
        const float rlo = __fdividef(1.f, dlo + dbuf[r_lo]);
        const float rhi = __fdividef(1.f, dhi + dbuf[r_hi]);
        float* olo = out + (size_t)(base + i0 + r_lo) * HID;
        float* ohi = out + (size_t)(base + i0 + r_hi) * HID;
#pragma unroll
        for (int nt = 0; nt < 8; nt++) {
            const int col = nt * 8 + 2 * tg;
            *(float2*)&olo[col] = make_float2((c[nt][0] + cbuf[r_lo * 64 + col]) * rlo,
                                              (c[nt][1] + cbuf[r_lo * 64 + col + 1]) * rlo);
            *(float2*)&ohi[col] = make_float2((c[nt][2] + cbuf[r_hi * 64 + col]) * rhi,
                                              (c[nt][3] + cbuf[r_hi * 64 + col + 1]) * rhi);
        }
    }
}

// ---------------------------------------------------------------------------
extern "C" void kernel_launch(void* const* d_in, const int* in_sizes, int n_in,
                              void* d_out, int out_size) {
    const float* X  = (const float*)d_in[0];   // node_features [8,2048,256]
    const int*   A  = (const int*)d_in[1];     // adj [8,2048,2048]
    const float* W  = (const float*)d_in[2];   // W [256,64]
    const float* av = (const float*)d_in[3];   // a [128,1]
    float* out = (float*)d_out;                // [8,2048,64] f32

    cudaFuncSetAttribute(gemm_wh, cudaFuncAttributeMaxDynamicSharedMemorySize,
                         SMEM_GW);
    cudaFuncSetAttribute(gat_main, cudaFuncAttributeMaxDynamicSharedMemorySize,
                         SMEM_DYN);

    gemm_wh<<<(B_ * N_) / 128, 256, SMEM_GW>>>(X, W, av);
    gat_main<<<dim3(B_ * (N_ / TI)), 512, SMEM_DYN>>>(A, out);
}